// round 16
// baseline (speedup 1.0000x reference)
#include <cuda_runtime.h>
#include <cuda_fp16.h>
#include <cstdint>
#include <cmath>

// scratch: mid tensor x [4,128,256,256] fp16, gated tensor [4,64,256,256] fp16
static __device__ __align__(16) __half g_xmid[(size_t)4 * 128 * 256 * 256];
static __device__ __align__(16) __half g_gate[(size_t)4 * 64 * 256 * 256];

typedef unsigned long long ull;

// ---------------------------------------------------------------------------
// f32x2 packed helpers. Packed complex convention: lo = re, hi = im.
// ---------------------------------------------------------------------------
__device__ __forceinline__ ull pack2(float lo, float hi)
{
    ull r;
    asm("mov.b64 %0, {%1, %2};" : "=l"(r) : "f"(lo), "f"(hi));
    return r;
}
__device__ __forceinline__ void unpack2(ull v, float& lo, float& hi)
{
    asm("mov.b64 {%0, %1}, %2;" : "=f"(lo), "=f"(hi) : "l"(v));
}
__device__ __forceinline__ ull fma2(ull a, ull b, ull c)
{
    ull d;
    asm("fma.rn.f32x2 %0, %1, %2, %3;" : "=l"(d) : "l"(a), "l"(b), "l"(c));
    return d;
}
__device__ __forceinline__ ull cadd(ull a, ull b)
{
    ull d;
    asm("add.rn.f32x2 %0, %1, %2;" : "=l"(d) : "l"(a), "l"(b));
    return d;
}
__device__ __forceinline__ ull cmul2(ull a, ull b)
{
    ull d;
    asm("mul.rn.f32x2 %0, %1, %2;" : "=l"(d) : "l"(a), "l"(b));
    return d;
}
// a - b, exact (multiply by -1 is exact)
__device__ __forceinline__ ull csub(ull a, ull b)
{
    const ull NEG1 = pack2(-1.0f, -1.0f);
    return fma2(NEG1, b, a);
}
__device__ __forceinline__ float fneg(float x)
{
    return __int_as_float(__float_as_int(x) ^ 0x80000000);
}
// conj: flip sign of imag (hi) half
__device__ __forceinline__ ull cconj(ull v) { return v ^ 0x8000000000000000ULL; }
// (-i)*v = (im, -re)
__device__ __forceinline__ ull mneg_i(ull v)
{
    float r, i; unpack2(v, r, i);
    return pack2(i, fneg(r));
}
// (+i)*v = (-im, re)
__device__ __forceinline__ ull mpos_i(ull v)
{
    float r, i; unpack2(v, r, i);
    return pack2(fneg(i), r);
}
// real scalar * complex
__device__ __forceinline__ ull cscale(ull v, float f) { return cmul2(pack2(f, f), v); }

__device__ __forceinline__ ull shfl64(ull v, int m)
{
    return __shfl_xor_sync(0xffffffffu, v, m);
}

// ---------------------------------------------------------------------------
// Packed 8-point complex FFT. fwd=true: e^{-i}, false: e^{+i}. NO scaling.
// ---------------------------------------------------------------------------
__device__ __forceinline__ void cfft8p(ull z[8], const bool fwd)
{
    const float cc = 0.70710678118654752440f;
    ull t0 = cadd(z[0], z[4]);
    ull t1 = csub(z[0], z[4]);
    ull t2 = cadd(z[2], z[6]);
    ull t3 = csub(z[2], z[6]);
    ull E0 = cadd(t0, t2);
    ull E2 = csub(t0, t2);
    ull w3 = fwd ? mneg_i(t3) : mpos_i(t3);
    ull E1 = cadd(t1, w3);
    ull E3 = csub(t1, w3);
    ull u0 = cadd(z[1], z[5]);
    ull u1 = csub(z[1], z[5]);
    ull u2 = cadd(z[3], z[7]);
    ull u3 = csub(z[3], z[7]);
    ull O0 = cadd(u0, u2);
    ull O2 = csub(u0, u2);
    ull wu = fwd ? mneg_i(u3) : mpos_i(u3);
    ull O1 = cadd(u1, wu);
    ull O3 = csub(u1, wu);
    ull T0 = O0;
    ull s1 = fwd ? mneg_i(O1) : mpos_i(O1);
    ull T1 = cscale(cadd(O1, s1), cc);
    ull T2 = fwd ? mneg_i(O2) : mpos_i(O2);
    ull s3 = fwd ? mneg_i(O3) : mpos_i(O3);
    ull T3 = cscale(csub(s3, O3), cc);
    z[0] = cadd(E0, T0); z[4] = csub(E0, T0);
    z[1] = cadd(E1, T1); z[5] = csub(E1, T1);
    z[2] = cadd(E2, T2); z[6] = csub(E2, T2);
    z[3] = cadd(E3, T3); z[7] = csub(E3, T3);
}

// tile decode: t in [0, 2048): b = t>>9, ph = (t>>4)&31, pw16 = t&15
#define NT_TILES 2048
#define MID_PITCH 136   // halves; 272 B = 16B-aligned rows, conflict-free per
                        // quarter-warp phase (group idx 17l mod 8 = l mod 8)

// ---------------------------------------------------------------------------
// Kernel F9 (512 threads, persistent): r12 pipeline + paired real inverse in
// stage C (2 cfft8p instead of 4). Pitch 136 (alignment-safe).
// smem: sWT 16384 fl | sFilt 5248 fl | sIn 16384 fl | sMid(half) [256][136]
// total = 221,696 B -> 1 block/SM
// ---------------------------------------------------------------------------
__global__ void __launch_bounds__(512, 1) kF9(const float* __restrict__ img,
                                              const float* __restrict__ evt,
                                              const float* __restrict__ w_img,
                                              const float* __restrict__ w_evt,
                                              const float* __restrict__ filt)
{
    extern __shared__ float sm[];
    float*  sWT   = sm;                                    // [64][256]
    float*  sFilt = sm + 16384;                            // [128][41]
    float*  sIn   = sm + 21632;                            // [2][64][128]
    __half* sMidH = reinterpret_cast<__half*>(sm + 38016); // [256][136]

    const int tid    = threadIdx.x;
    const int stride = gridDim.x;
    const float HSC = 0.5f / 64.0f;   // 0.5 (hermitian split) * 1/64 (irfft2)

    const float4* img4 = reinterpret_cast<const float4*>(img);
    const float4* evt4 = reinterpret_cast<const float4*>(evt);

    // one-time prologue: weights (transposed) + pre-scaled filter
    for (int i = tid; i < 64 * 128; i += 512) {
        int k = i >> 7, o = i & 127;
        sWT[k * 256 + o]       = w_img[o * 64 + k];
        sWT[k * 256 + 128 + o] = w_evt[o * 64 + k];
    }
    for (int i = tid; i < 128 * 40; i += 512) {
        int o = i / 40, j = i - o * 40;
        sFilt[o * 41 + j] = filt[i] * HSC;
    }

    int t = blockIdx.x;
    if (t < NT_TILES) {
        const int b0 = t >> 9, ph0 = (t >> 4) & 31, pw0 = t & 15;
        for (int i = tid; i < 64 * 32; i += 512) {
            int c = i >> 5, q4 = i & 31;
            int r = q4 >> 2, xx = q4 & 3;
            int g4 = (((b0 * 64 + c) * 256 + ph0 * 8 + r) * 256 + pw0 * 16) / 4 + xx;
            *reinterpret_cast<float4*>(&sIn[c * 128 + q4 * 4])        = img4[g4];
            *reinterpret_cast<float4*>(&sIn[8192 + c * 128 + q4 * 4]) = evt4[g4];
        }
    }
    __syncthreads();

    // GEMM thread tile: 8 slots x 8 px
    const int rb = tid >> 4, cb = tid & 15;
    const int r0 = rb * 8, c0 = cb * 8;
    const float* pin = sIn + ((r0 >= 128) ? 8192 : 0);

    // FFT role: 2 threads per (channel, patch)
    const int lane = tid & 31;
    const int w    = tid >> 5;
    const int h    = lane >> 4;
    const int item = w * 16 + (lane & 15);
    const int o    = item & 127;
    const int pp   = item >> 7;
    const bool hB  = (h == 1);
    const float C7 = 0.70710678118654752440f;
    const __half* rowI = sMidH + o * MID_PITCH + pp * 8;
    const __half* rowE = sMidH + (128 + o) * MID_PITCH + pp * 8;
    const float* fo = sFilt + o * 41;

    const ull C7P  = pack2(C7, C7);
    const ull NC7P = pack2(-C7, -C7);
    const ull HALF = pack2(0.5f, 0.5f);
    const ull ONE0 = pack2(1.0f, 0.0f);

    while (t < NT_TILES) {
        const int b    = t >> 9;
        const int ph   = (t >> 4) & 31;
        const int pw16 = t & 15;
        const int tn   = t + stride;

        // ---- GEMM: 256 slots x 128 px, k=64 (f32x2) ----
        ull acc[32];
#pragma unroll
        for (int i = 0; i < 32; i++) acc[i] = 0ULL;
#pragma unroll 4
        for (int k = 0; k < 64; k++) {
            float4 w0 = *reinterpret_cast<const float4*>(&sWT[k * 256 + r0]);
            float4 w1 = *reinterpret_cast<const float4*>(&sWT[k * 256 + r0 + 4]);
            ulonglong2 xa = *reinterpret_cast<const ulonglong2*>(&pin[k * 128 + c0]);
            ulonglong2 xb = *reinterpret_cast<const ulonglong2*>(&pin[k * 128 + c0 + 4]);
            ull xv[4] = {xa.x, xa.y, xb.x, xb.y};
            float wf[8] = {w0.x, w0.y, w0.z, w0.w, w1.x, w1.y, w1.z, w1.w};
#pragma unroll
            for (int i = 0; i < 8; i++) {
                ull wp = pack2(wf[i], wf[i]);
#pragma unroll
                for (int j = 0; j < 4; j++)
                    acc[i * 4 + j] = fma2(wp, xv[j], acc[i * 4 + j]);
            }
        }
        __syncthreads();   // sIn reads done; prev FFT done with sMid

        // ---- spill acc -> sMid fp16 ----
#pragma unroll
        for (int i = 0; i < 8; i++) {
            __half2 hh[4];
#pragma unroll
            for (int j = 0; j < 4; j++) {
                float lo, hi;
                unpack2(acc[i * 4 + j], lo, hi);
                hh[j] = __floats2half2_rn(lo, hi);
            }
            *reinterpret_cast<uint4*>(&sMidH[(r0 + i) * MID_PITCH + c0]) =
                *reinterpret_cast<uint4*>(hh);
        }
        // ---- preload pixels for next tile ----
        if (tn < NT_TILES) {
            const int bn = tn >> 9, phn = (tn >> 4) & 31, pwn = tn & 15;
            for (int i = tid; i < 64 * 32; i += 512) {
                int c = i >> 5, q4 = i & 31;
                int r = q4 >> 2, xx = q4 & 3;
                int g4 = (((bn * 64 + c) * 256 + phn * 8 + r) * 256 + pwn * 16) / 4 + xx;
                *reinterpret_cast<float4*>(&sIn[c * 128 + q4 * 4])        = img4[g4];
                *reinterpret_cast<float4*>(&sIn[8192 + c * 128 + q4 * 4]) = evt4[g4];
            }
        }
        __syncthreads();   // sMid + sIn(next) ready

        // ---- cooperative register FFT (packed complex) ----
        ull ZP[32];   // 4 local rows x 8 cols, packed (re, im)

        // stage A: row FFTs of z = img + i*event (rows h*4 .. h*4+3)
#pragma unroll
        for (int j = 0; j < 4; j++) {
            const int R = h * 4 + j;
            uint4 ra  = *reinterpret_cast<const uint4*>(rowI + R * 16);
            uint4 rb2 = *reinterpret_cast<const uint4*>(rowE + R * 16);
            const __half2* ha = reinterpret_cast<const __half2*>(&ra);
            const __half2* hb = reinterpret_cast<const __half2*>(&rb2);
            ull z[8];
#pragma unroll
            for (int tt = 0; tt < 4; tt++) {
                float2 fa = __half22float2(ha[tt]);
                float2 fb = __half22float2(hb[tt]);
                z[2 * tt]     = pack2(fa.x, fb.x);
                z[2 * tt + 1] = pack2(fa.y, fb.y);
            }
            cfft8p(z, true);
#pragma unroll
            for (int c = 0; c < 8; c++) ZP[j * 8 + c] = z[c];
        }

        // stage B-fwd: 8-pt column FFTs, DIF split across thread pair
#pragma unroll
        for (int c = 0; c < 8; c++) {
            ull l[4], r[4];
#pragma unroll
            for (int j = 0; j < 4; j++) l[j] = ZP[j * 8 + c];
#pragma unroll
            for (int j = 0; j < 4; j++) r[j] = shfl64(l[j], 16);
            ull tq[4];
            if (!hB) {
#pragma unroll
                for (int j = 0; j < 4; j++) tq[j] = cadd(l[j], r[j]);
            } else {
                ull d[4];
#pragma unroll
                for (int j = 0; j < 4; j++) d[j] = csub(r[j], l[j]);
                tq[0] = d[0];
                tq[1] = cscale(cadd(d[1], mneg_i(d[1])), C7);
                tq[2] = mneg_i(d[2]);
                tq[3] = cscale(csub(mneg_i(d[3]), d[3]), C7);
            }
            ull s0 = cadd(tq[0], tq[2]);
            ull s1 = csub(tq[0], tq[2]);
            ull s2 = cadd(tq[1], tq[3]);
            ull s3 = csub(tq[1], tq[3]);
            ull ws = mneg_i(s3);
            ZP[0 * 8 + c] = cadd(s0, s2);
            ZP[1 * 8 + c] = cadd(s1, ws);
            ZP[2 * 8 + c] = csub(s0, s2);
            ZP[3 * 8 + c] = csub(s1, ws);
        }

        // stage B-combine+inverse (packed): pairs (v, m=(8-v)&7)
        const int vv[5] = {0, 4, 1, 2, 3};
        const int mm[5] = {0, 4, 7, 6, 5};
#pragma unroll
        for (int pidx = 0; pidx < 5; pidx++) {
            const int v = vv[pidx], m = mm[pidx];
            ull x[4];
#pragma unroll
            for (int k = 0; k < 4; k++) {
                const int u  = 2 * k + h;
                const int kn = hB ? (3 - k) : ((4 - k) & 3);
                ull p  = ZP[k * 8 + v];
                ull cq = cconj(ZP[kn * 8 + m]);
                ull I  = cadd(p, cq);
                ull D  = csub(p, cq);
                ull E  = cscale(mneg_i(D), fo[u * 5 + v]);   // filter pre-scaled
                ull a  = fma2(HALF, I, ONE0);
                float ar, ai;
                unpack2(a, ar, ai);
                x[k] = fma2(pack2(ar, ar), E, cmul2(pack2(ai, ai), mpos_i(E)));
            }
            ull s0 = cadd(x[0], x[2]);
            ull s1 = csub(x[0], x[2]);
            ull s2 = cadd(x[1], x[3]);
            ull s3 = csub(x[1], x[3]);
            ull g0 = cadd(s0, s2);
            ull g2 = csub(s0, s2);
            ull wg = mpos_i(s3);
            ull g1 = cadd(s1, wg);
            ull g3 = csub(s1, wg);
            ull h0 = shfl64(g0, 16), h1 = shfl64(g1, 16);
            ull h2 = shfl64(g2, 16), h3 = shfl64(g3, 16);
            if (!hB) {   // z_j = G_j + W^{-j} H_j
                ZP[0 * 8 + v] = cadd(g0, h0);
                ZP[1 * 8 + v] = fma2(C7P, cadd(h1, mpos_i(h1)), g1);
                ZP[2 * 8 + v] = cadd(g2, mpos_i(h2));
                ZP[3 * 8 + v] = fma2(C7P, mpos_i(cadd(h3, mpos_i(h3))), g3);
            } else {     // z_{j+4} = H_j - W^{-j} G_j
                ZP[0 * 8 + v] = csub(h0, g0);
                ZP[1 * 8 + v] = fma2(NC7P, cadd(g1, mpos_i(g1)), h1);
                ZP[2 * 8 + v] = cadd(h2, mneg_i(g2));
                ZP[3 * 8 + v] = fma2(C7P, cadd(g3, mneg_i(g3)), h3);
            }
        }

        // stage C: row inverse. Each row's spectrum is hermitian -> real
        // output, so pair rows: ifft8(Za + i*Zb) = ra + i*rb EXACTLY.
        // 2 packed inverse FFTs instead of 4.
        __half* outp = g_xmid + (((size_t)(b * 128 + o) * 256 + ph * 8) * 256
                                 + pw16 * 16 + pp * 8);
#pragma unroll
        for (int jp = 0; jp < 2; jp++) {
            const int ja = 2 * jp, jb = 2 * jp + 1;
            const int Ra = h * 4 + ja;
            ull z[8];
#pragma unroll
            for (int v = 0; v < 5; v++)
                z[v] = cadd(ZP[ja * 8 + v], mpos_i(ZP[jb * 8 + v]));
            z[5] = cadd(cconj(ZP[ja * 8 + 3]), mpos_i(cconj(ZP[jb * 8 + 3])));
            z[6] = cadd(cconj(ZP[ja * 8 + 2]), mpos_i(cconj(ZP[jb * 8 + 2])));
            z[7] = cadd(cconj(ZP[ja * 8 + 1]), mpos_i(cconj(ZP[jb * 8 + 1])));
            cfft8p(z, false);
            // lo = row Ra pixels, hi = row Ra+1 pixels
            __half2 ha[4], hb2[4];
#pragma unroll
            for (int tt = 0; tt < 4; tt++) {
                float lo0, hi0, lo1, hi1;
                unpack2(z[2 * tt], lo0, hi0);
                unpack2(z[2 * tt + 1], lo1, hi1);
                ha[tt]  = __floats2half2_rn(lo0, lo1);
                hb2[tt] = __floats2half2_rn(hi0, hi1);
            }
            *reinterpret_cast<uint4*>(outp + (size_t)Ra * 256) =
                *reinterpret_cast<uint4*>(ha);
            *reinterpret_cast<uint4*>(outp + (size_t)(Ra + 1) * 256) =
                *reinterpret_cast<uint4*>(hb2);
        }

        t = tn;
    }
}

// ---------------------------------------------------------------------------
// Kernel DW2: depthwise 3x3 (SAME) + exact GELU gate, vectorized fp16 halo.
// ---------------------------------------------------------------------------
__global__ void __launch_bounds__(256) kDW2(const float* __restrict__ w_dw)
{
    __shared__ __half sH2[2 * 18 * 80];

    const int tid = threadIdx.x;
    const int b = blockIdx.z >> 6, c = blockIdx.z & 63;
    const int x0 = blockIdx.x * 64, y0 = blockIdx.y * 16;

    float w1[9], w2[9];
#pragma unroll
    for (int j = 0; j < 9; j++) {
        w1[j] = w_dw[c * 9 + j];
        w2[j] = w_dw[(c + 64) * 9 + j];
    }

    const __half* src0 = g_xmid + (size_t)(b * 128 + c) * 65536;
    const __half* src1 = src0 + (size_t)64 * 65536;
    const __half zeroh = __float2half(0.f);

    for (int i = tid; i < 360; i += 256) {
        const int ch  = i / 180;
        const int rem = i - ch * 180;
        const int y = rem / 10, chk = rem - y * 10;
        const int gy = y0 + y - 1;
        const int gxc = x0 - 8 + chk * 8;
        uint4 v = make_uint4(0u, 0u, 0u, 0u);
        if (gy >= 0 && gy < 256) {
            const __half* src = (ch ? src1 : src0) + (size_t)gy * 256;
            if (gxc >= 0 && gxc + 8 <= 256) {
                v = *reinterpret_cast<const uint4*>(src + gxc);
            } else {
                __half2 h2[4];
#pragma unroll
                for (int e = 0; e < 4; e++) {
                    int g0 = gxc + 2 * e, g1 = g0 + 1;
                    __half a = (g0 >= 0 && g0 < 256) ? src[g0] : zeroh;
                    __half d = (g1 >= 0 && g1 < 256) ? src[g1] : zeroh;
                    h2[e] = __halves2half2(a, d);
                }
                v = *reinterpret_cast<uint4*>(h2);
            }
        }
        *reinterpret_cast<uint4*>(&sH2[ch * 1440 + y * 80 + chk * 8]) = v;
    }
    __syncthreads();

    const int px = tid & 63, ty = tid >> 6;
    __half* dst = g_gate + (size_t)(b * 64 + c) * 65536;
#pragma unroll
    for (int yy = 0; yy < 4; yy++) {
        int py = ty * 4 + yy;
        float a = 0.f, bb = 0.f;
#pragma unroll
        for (int dy = 0; dy < 3; dy++)
#pragma unroll
            for (int dx = 0; dx < 3; dx++) {
                const int hoff = (py + dy) * 80 + px + dx + 7;
                a  = fmaf(__half2float(sH2[hoff]),        w1[dy * 3 + dx], a);
                bb = fmaf(__half2float(sH2[1440 + hoff]), w2[dy * 3 + dx], bb);
            }
        float gl = 0.5f * a * (1.0f + erff(a * 0.70710678118654752f));
        dst[(size_t)(y0 + py) * 256 + x0 + px] = __float2half_rn(gl * bb);
    }
}

// ---------------------------------------------------------------------------
// Kernel Out3: persistent 1x1 projection, grid 256 (exactly 4 rows/block).
// smem: sG[64][256] fp32 + sWoT[64][64] = 81,920 B (2 blocks/SM)
// ---------------------------------------------------------------------------
__global__ void __launch_bounds__(256, 2) kOut3(const float* __restrict__ w_out,
                                                float* __restrict__ out)
{
    extern __shared__ float sm[];
    float* sG   = sm;          // [64][256]
    float* sWoT = sm + 16384;  // [64][64]

    const int tid    = threadIdx.x;
    const int stride = gridDim.x;

    for (int i = tid; i < 64 * 64; i += 256) {
        int k = i >> 6, o = i & 63;
        sWoT[k * 64 + o] = w_out[o * 64 + k];
    }

    const int ob = tid >> 5, pb = tid & 31;
    const int oc0 = ob * 8, p0 = pb * 8;

    for (int rr = blockIdx.x; rr < 1024; rr += stride) {
        const int b = rr >> 8, y = rr & 255;

        __syncthreads();
        for (int i = tid; i < 2048; i += 256) {
            int k = i >> 5, p8 = i & 31;
            uint4 rh = *reinterpret_cast<const uint4*>(
                g_gate + (size_t)(b * 64 + k) * 65536 + (size_t)y * 256 + p8 * 8);
            const __half2* hp = reinterpret_cast<const __half2*>(&rh);
            float v[8];
#pragma unroll
            for (int tt = 0; tt < 4; tt++) {
                float2 f2 = __half22float2(hp[tt]);
                v[2 * tt] = f2.x; v[2 * tt + 1] = f2.y;
            }
            float4 q0 = {v[0], v[1], v[2], v[3]};
            float4 q1 = {v[4], v[5], v[6], v[7]};
            *reinterpret_cast<float4*>(&sG[k * 256 + p8 * 8])     = q0;
            *reinterpret_cast<float4*>(&sG[k * 256 + p8 * 8 + 4]) = q1;
        }
        __syncthreads();

        ull acc[32];
#pragma unroll
        for (int i = 0; i < 32; i++) acc[i] = 0ULL;
#pragma unroll 8
        for (int k = 0; k < 64; k++) {
            float4 w0 = *reinterpret_cast<const float4*>(&sWoT[k * 64 + oc0]);
            float4 w1 = *reinterpret_cast<const float4*>(&sWoT[k * 64 + oc0 + 4]);
            ulonglong2 ga = *reinterpret_cast<const ulonglong2*>(&sG[k * 256 + p0]);
            ulonglong2 gb = *reinterpret_cast<const ulonglong2*>(&sG[k * 256 + p0 + 4]);
            ull gv[4] = {ga.x, ga.y, gb.x, gb.y};
            float wf[8] = {w0.x, w0.y, w0.z, w0.w, w1.x, w1.y, w1.z, w1.w};
#pragma unroll
            for (int i = 0; i < 8; i++) {
                ull wp = pack2(wf[i], wf[i]);
#pragma unroll
                for (int j = 0; j < 4; j++)
                    acc[i * 4 + j] = fma2(wp, gv[j], acc[i * 4 + j]);
            }
        }
#pragma unroll
        for (int i = 0; i < 8; i++) {
            float v[8];
#pragma unroll
            for (int j = 0; j < 4; j++) unpack2(acc[i * 4 + j], v[2 * j], v[2 * j + 1]);
            size_t gaddr = ((size_t)(b * 64 + oc0 + i) * 256 + y) * 256 + p0;
            float4 q0 = {v[0], v[1], v[2], v[3]};
            float4 q1 = {v[4], v[5], v[6], v[7]};
            *reinterpret_cast<float4*>(&out[gaddr])     = q0;
            *reinterpret_cast<float4*>(&out[gaddr + 4]) = q1;
        }
    }
}

// ---------------------------------------------------------------------------
extern "C" void kernel_launch(void* const* d_in, const int* in_sizes, int n_in,
                              void* d_out, int out_size)
{
    const float* img   = (const float*)d_in[0];
    const float* evt   = (const float*)d_in[1];
    const float* w_img = (const float*)d_in[2];
    const float* w_evt = (const float*)d_in[3];
    const float* w_dw  = (const float*)d_in[4];
    const float* filt  = (const float*)d_in[5];
    const float* w_out = (const float*)d_in[6];
    float* out = (float*)d_out;

    const int smemF = 38016 * 4 + 256 * MID_PITCH * 2;  // 221,696 B -> 1 block/SM
    const int smemO = 20480 * 4;                        //  81,920 B -> 2 blocks/SM
    cudaFuncSetAttribute(kF9,   cudaFuncAttributeMaxDynamicSharedMemorySize, smemF);
    cudaFuncSetAttribute(kOut3, cudaFuncAttributeMaxDynamicSharedMemorySize, smemO);

    kF9<<<296, 512, smemF>>>(img, evt, w_img, w_evt, filt);
    kDW2<<<dim3(4, 16, 256), 256>>>(w_dw);
    kOut3<<<256, 256, smemO>>>(w_out, out);
}

// round 17
// speedup vs baseline: 1.5464x; 1.5464x over previous
#include <cuda_runtime.h>
#include <cuda_fp16.h>
#include <cstdint>
#include <cmath>

// scratch: mid tensor x [4,128,256,256] fp16, gated tensor [4,64,256,256] fp16
static __device__ __align__(16) __half g_xmid[(size_t)4 * 128 * 256 * 256];
static __device__ __align__(16) __half g_gate[(size_t)4 * 64 * 256 * 256];

typedef unsigned long long ull;

// ---------------------------------------------------------------------------
// f32x2 packed helpers. Packed complex convention: lo = re, hi = im.
// ---------------------------------------------------------------------------
__device__ __forceinline__ ull pack2(float lo, float hi)
{
    ull r;
    asm("mov.b64 %0, {%1, %2};" : "=l"(r) : "f"(lo), "f"(hi));
    return r;
}
__device__ __forceinline__ void unpack2(ull v, float& lo, float& hi)
{
    asm("mov.b64 {%0, %1}, %2;" : "=f"(lo), "=f"(hi) : "l"(v));
}
__device__ __forceinline__ ull fma2(ull a, ull b, ull c)
{
    ull d;
    asm("fma.rn.f32x2 %0, %1, %2, %3;" : "=l"(d) : "l"(a), "l"(b), "l"(c));
    return d;
}
__device__ __forceinline__ ull cadd(ull a, ull b)
{
    ull d;
    asm("add.rn.f32x2 %0, %1, %2;" : "=l"(d) : "l"(a), "l"(b));
    return d;
}
__device__ __forceinline__ ull cmul2(ull a, ull b)
{
    ull d;
    asm("mul.rn.f32x2 %0, %1, %2;" : "=l"(d) : "l"(a), "l"(b));
    return d;
}
__device__ __forceinline__ ull csub(ull a, ull b)
{
    const ull NEG1 = pack2(-1.0f, -1.0f);
    return fma2(NEG1, b, a);
}
__device__ __forceinline__ float fneg(float x)
{
    return __int_as_float(__float_as_int(x) ^ 0x80000000);
}
__device__ __forceinline__ ull cconj(ull v) { return v ^ 0x8000000000000000ULL; }
__device__ __forceinline__ ull mneg_i(ull v)
{
    float r, i; unpack2(v, r, i);
    return pack2(i, fneg(r));
}
__device__ __forceinline__ ull mpos_i(ull v)
{
    float r, i; unpack2(v, r, i);
    return pack2(fneg(i), r);
}
__device__ __forceinline__ ull cscale(ull v, float f) { return cmul2(pack2(f, f), v); }

__device__ __forceinline__ ull shfl64(ull v, int m)
{
    return __shfl_xor_sync(0xffffffffu, v, m);
}

// fp16 pack helper
__device__ __forceinline__ uint32_t h2u(float a, float b)
{
    __half2 h = __floats2half2_rn(a, b);
    return *reinterpret_cast<uint32_t*>(&h);
}

// HMMA m16n8k16 row.col f32 = f16*f16 + f32
__device__ __forceinline__ void mma16816(float& d0, float& d1, float& d2, float& d3,
                                         uint32_t a0, uint32_t a1, uint32_t a2, uint32_t a3,
                                         uint32_t b0, uint32_t b1)
{
    asm volatile(
        "mma.sync.aligned.m16n8k16.row.col.f32.f16.f16.f32 "
        "{%0,%1,%2,%3}, {%4,%5,%6,%7}, {%8,%9}, {%0,%1,%2,%3};"
        : "+f"(d0), "+f"(d1), "+f"(d2), "+f"(d3)
        : "r"(a0), "r"(a1), "r"(a2), "r"(a3), "r"(b0), "r"(b1));
}

// ---------------------------------------------------------------------------
// Packed 8-point complex FFT. fwd=true: e^{-i}, false: e^{+i}. NO scaling.
// ---------------------------------------------------------------------------
__device__ __forceinline__ void cfft8p(ull z[8], const bool fwd)
{
    const float cc = 0.70710678118654752440f;
    ull t0 = cadd(z[0], z[4]);
    ull t1 = csub(z[0], z[4]);
    ull t2 = cadd(z[2], z[6]);
    ull t3 = csub(z[2], z[6]);
    ull E0 = cadd(t0, t2);
    ull E2 = csub(t0, t2);
    ull w3 = fwd ? mneg_i(t3) : mpos_i(t3);
    ull E1 = cadd(t1, w3);
    ull E3 = csub(t1, w3);
    ull u0 = cadd(z[1], z[5]);
    ull u1 = csub(z[1], z[5]);
    ull u2 = cadd(z[3], z[7]);
    ull u3 = csub(z[3], z[7]);
    ull O0 = cadd(u0, u2);
    ull O2 = csub(u0, u2);
    ull wu = fwd ? mneg_i(u3) : mpos_i(u3);
    ull O1 = cadd(u1, wu);
    ull O3 = csub(u1, wu);
    ull T0 = O0;
    ull s1 = fwd ? mneg_i(O1) : mpos_i(O1);
    ull T1 = cscale(cadd(O1, s1), cc);
    ull T2 = fwd ? mneg_i(O2) : mpos_i(O2);
    ull s3 = fwd ? mneg_i(O3) : mpos_i(O3);
    ull T3 = cscale(csub(s3, O3), cc);
    z[0] = cadd(E0, T0); z[4] = csub(E0, T0);
    z[1] = cadd(E1, T1); z[5] = csub(E1, T1);
    z[2] = cadd(E2, T2); z[6] = csub(E2, T2);
    z[3] = cadd(E3, T3); z[7] = csub(E3, T3);
}

// tile decode: t in [0, 2048): b = t>>9, ph = (t>>4)&31, pw16 = t&15
#define NT_TILES 2048
#define MID_PITCH 136   // halves, 272B rows (16B aligned)
#define B_PITCH   136   // half2 units per k2-row of pixel tensor

// ---------------------------------------------------------------------------
// Kernel F10 (512 threads, persistent): tensor-core GEMM (HMMA fp16->fp32,
// weights register-resident) + packed register FFT (unchanged from r14/r16).
// smem (floats): sFilt[128][41]=5248 | sInI/sInE half2 [32][136] (8704 fl) |
//                sMid half [256][136] (17408 fl)  -> 125,440 B total
// ---------------------------------------------------------------------------
__global__ void __launch_bounds__(512, 1) kF10(const float* __restrict__ img,
                                               const float* __restrict__ evt,
                                               const float* __restrict__ w_img,
                                               const float* __restrict__ w_evt,
                                               const float* __restrict__ filt)
{
    extern __shared__ float sm[];
    float*   sFilt = sm;                                        // [128][41]
    __half2* sInI  = reinterpret_cast<__half2*>(sm + 5248);     // [32][136]
    __half2* sInE  = reinterpret_cast<__half2*>(sm + 9600);     // [32][136]
    __half*  sMidH = reinterpret_cast<__half*>(sm + 13952);     // [256][136]

    const int tid    = threadIdx.x;
    const int stride = gridDim.x;
    const float HSC = 0.5f / 64.0f;

    const float4* img4 = reinterpret_cast<const float4*>(img);
    const float4* evt4 = reinterpret_cast<const float4*>(evt);

    // roles
    const int lane = tid & 31;
    const int wm   = tid >> 5;           // warp id: GEMM m-tile
    const int g    = lane >> 2;          // mma group id (0..7)
    const int tig  = lane & 3;           // thread-in-group (0..3)
    const int m0   = wm * 16;            // global slot base for this warp

    // FFT role: 2 threads per (channel, patch)
    const int h    = lane >> 4;
    const int item = wm * 16 + (lane & 15);
    const int o    = item & 127;
    const int pp   = item >> 7;
    const bool hB  = (h == 1);
    const float C7 = 0.70710678118654752440f;
    const __half* rowI = sMidH + o * MID_PITCH + pp * 8;
    const __half* rowE = sMidH + (128 + o) * MID_PITCH + pp * 8;
    const float* fo = sFilt + o * 41;

    const ull C7P  = pack2(C7, C7);
    const ull NC7P = pack2(-C7, -C7);
    const ull HALF = pack2(0.5f, 0.5f);
    const ull ONE0 = pack2(1.0f, 0.0f);

    // one-time prologue: filter (pre-scaled) + A fragments into registers
    for (int i = tid; i < 128 * 40; i += 512) {
        int oo = i / 40, j = i - oo * 40;
        sFilt[oo * 41 + j] = filt[i] * HSC;
    }
    uint32_t Areg[16];
    {
        const float* Wsrc = (wm < 8) ? w_img : w_evt;
        const int ms = (wm & 7) * 16;
        const int r1 = ms + g, r2 = ms + g + 8;
#pragma unroll
        for (int ks = 0; ks < 4; ks++) {
            const int k0 = ks * 16 + tig * 2;
            Areg[ks * 4 + 0] = h2u(Wsrc[r1 * 64 + k0],     Wsrc[r1 * 64 + k0 + 1]);
            Areg[ks * 4 + 1] = h2u(Wsrc[r2 * 64 + k0],     Wsrc[r2 * 64 + k0 + 1]);
            Areg[ks * 4 + 2] = h2u(Wsrc[r1 * 64 + k0 + 8], Wsrc[r1 * 64 + k0 + 9]);
            Areg[ks * 4 + 3] = h2u(Wsrc[r2 * 64 + k0 + 8], Wsrc[r2 * 64 + k0 + 9]);
        }
    }

    int t = blockIdx.x;
    if (t < NT_TILES) {
        // stage pixels for first tile: k2-interleaved half2 [32][136]
        const int b0 = t >> 9, ph0 = (t >> 4) & 31, pw0 = t & 15;
        for (int i = tid; i < 1024; i += 512) {
            const int k2 = i >> 5, pxg = i & 31;
            const int r = pxg >> 2, xx4 = pxg & 3;
            const int gb = (((b0 * 64 + 2 * k2) * 256 + ph0 * 8 + r) * 256 + pw0 * 16) / 4 + xx4;
            float4 f0 = img4[gb];
            float4 f1 = img4[gb + 16384];
            __half2 hh[4] = {__floats2half2_rn(f0.x, f1.x), __floats2half2_rn(f0.y, f1.y),
                             __floats2half2_rn(f0.z, f1.z), __floats2half2_rn(f0.w, f1.w)};
            *reinterpret_cast<uint4*>(&sInI[k2 * B_PITCH + pxg * 4]) =
                *reinterpret_cast<uint4*>(hh);
            float4 e0 = evt4[gb];
            float4 e1 = evt4[gb + 16384];
            __half2 he[4] = {__floats2half2_rn(e0.x, e1.x), __floats2half2_rn(e0.y, e1.y),
                             __floats2half2_rn(e0.z, e1.z), __floats2half2_rn(e0.w, e1.w)};
            *reinterpret_cast<uint4*>(&sInE[k2 * B_PITCH + pxg * 4]) =
                *reinterpret_cast<uint4*>(he);
        }
    }
    __syncthreads();

    const __half2* Bsrc = (wm < 8) ? sInI : sInE;

    while (t < NT_TILES) {
        const int b    = t >> 9;
        const int ph   = (t >> 4) & 31;
        const int pw16 = t & 15;
        const int tn   = t + stride;

        // ---- GEMM: warp = 16 slots x 128 px, HMMA m16n8k16, 64 mma ----
        float acc[64];
#pragma unroll
        for (int i = 0; i < 64; i++) acc[i] = 0.f;
#pragma unroll
        for (int ks = 0; ks < 4; ks++) {
            const uint32_t a0 = Areg[ks * 4 + 0], a1 = Areg[ks * 4 + 1];
            const uint32_t a2 = Areg[ks * 4 + 2], a3 = Areg[ks * 4 + 3];
            const int kr0 = (8 * ks + tig) * B_PITCH + g;
            const int kr1 = (8 * ks + 4 + tig) * B_PITCH + g;
#pragma unroll
            for (int nt = 0; nt < 16; nt++) {
                uint32_t bb0 = *reinterpret_cast<const uint32_t*>(&Bsrc[kr0 + nt * 8]);
                uint32_t bb1 = *reinterpret_cast<const uint32_t*>(&Bsrc[kr1 + nt * 8]);
                mma16816(acc[nt * 4 + 0], acc[nt * 4 + 1], acc[nt * 4 + 2], acc[nt * 4 + 3],
                         a0, a1, a2, a3, bb0, bb1);
            }
        }
        __syncthreads();   // GEMM reads of sIn done; prev FFT done with sMid

        // ---- spill D fragments -> sMid fp16 ----
#pragma unroll
        for (int nt = 0; nt < 16; nt++) {
            __half2 lo = __floats2half2_rn(acc[nt * 4 + 0], acc[nt * 4 + 1]);
            __half2 hi = __floats2half2_rn(acc[nt * 4 + 2], acc[nt * 4 + 3]);
            *reinterpret_cast<__half2*>(&sMidH[(m0 + g) * MID_PITCH + nt * 8 + tig * 2]) = lo;
            *reinterpret_cast<__half2*>(&sMidH[(m0 + g + 8) * MID_PITCH + nt * 8 + tig * 2]) = hi;
        }
        // ---- preload pixels for next tile ----
        if (tn < NT_TILES) {
            const int bn = tn >> 9, phn = (tn >> 4) & 31, pwn = tn & 15;
            for (int i = tid; i < 1024; i += 512) {
                const int k2 = i >> 5, pxg = i & 31;
                const int r = pxg >> 2, xx4 = pxg & 3;
                const int gb = (((bn * 64 + 2 * k2) * 256 + phn * 8 + r) * 256 + pwn * 16) / 4 + xx4;
                float4 f0 = img4[gb];
                float4 f1 = img4[gb + 16384];
                __half2 hh[4] = {__floats2half2_rn(f0.x, f1.x), __floats2half2_rn(f0.y, f1.y),
                                 __floats2half2_rn(f0.z, f1.z), __floats2half2_rn(f0.w, f1.w)};
                *reinterpret_cast<uint4*>(&sInI[k2 * B_PITCH + pxg * 4]) =
                    *reinterpret_cast<uint4*>(hh);
                float4 e0 = evt4[gb];
                float4 e1 = evt4[gb + 16384];
                __half2 he[4] = {__floats2half2_rn(e0.x, e1.x), __floats2half2_rn(e0.y, e1.y),
                                 __floats2half2_rn(e0.z, e1.z), __floats2half2_rn(e0.w, e1.w)};
                *reinterpret_cast<uint4*>(&sInE[k2 * B_PITCH + pxg * 4]) =
                    *reinterpret_cast<uint4*>(he);
            }
        }
        __syncthreads();   // sMid + sIn(next) ready

        // ---- cooperative register FFT (packed complex), unchanged ----
        ull ZP[32];

        // stage A: row FFTs of z = img + i*event (rows h*4 .. h*4+3)
#pragma unroll
        for (int j = 0; j < 4; j++) {
            const int R = h * 4 + j;
            uint4 ra  = *reinterpret_cast<const uint4*>(rowI + R * 16);
            uint4 rb2 = *reinterpret_cast<const uint4*>(rowE + R * 16);
            const __half2* ha = reinterpret_cast<const __half2*>(&ra);
            const __half2* hb = reinterpret_cast<const __half2*>(&rb2);
            ull z[8];
#pragma unroll
            for (int tt = 0; tt < 4; tt++) {
                float2 fa = __half22float2(ha[tt]);
                float2 fb = __half22float2(hb[tt]);
                z[2 * tt]     = pack2(fa.x, fb.x);
                z[2 * tt + 1] = pack2(fa.y, fb.y);
            }
            cfft8p(z, true);
#pragma unroll
            for (int c = 0; c < 8; c++) ZP[j * 8 + c] = z[c];
        }

        // stage B-fwd: column FFTs, DIF split across thread pair
#pragma unroll
        for (int c = 0; c < 8; c++) {
            ull l[4], r[4];
#pragma unroll
            for (int j = 0; j < 4; j++) l[j] = ZP[j * 8 + c];
#pragma unroll
            for (int j = 0; j < 4; j++) r[j] = shfl64(l[j], 16);
            ull tq[4];
            if (!hB) {
#pragma unroll
                for (int j = 0; j < 4; j++) tq[j] = cadd(l[j], r[j]);
            } else {
                ull d[4];
#pragma unroll
                for (int j = 0; j < 4; j++) d[j] = csub(r[j], l[j]);
                tq[0] = d[0];
                tq[1] = cscale(cadd(d[1], mneg_i(d[1])), C7);
                tq[2] = mneg_i(d[2]);
                tq[3] = cscale(csub(mneg_i(d[3]), d[3]), C7);
            }
            ull s0 = cadd(tq[0], tq[2]);
            ull s1 = csub(tq[0], tq[2]);
            ull s2 = cadd(tq[1], tq[3]);
            ull s3 = csub(tq[1], tq[3]);
            ull ws = mneg_i(s3);
            ZP[0 * 8 + c] = cadd(s0, s2);
            ZP[1 * 8 + c] = cadd(s1, ws);
            ZP[2 * 8 + c] = csub(s0, s2);
            ZP[3 * 8 + c] = csub(s1, ws);
        }

        // stage B-combine+inverse
        const int vv[5] = {0, 4, 1, 2, 3};
        const int mm[5] = {0, 4, 7, 6, 5};
#pragma unroll
        for (int pidx = 0; pidx < 5; pidx++) {
            const int v = vv[pidx], m = mm[pidx];
            ull x[4];
#pragma unroll
            for (int k = 0; k < 4; k++) {
                const int u  = 2 * k + h;
                const int kn = hB ? (3 - k) : ((4 - k) & 3);
                ull p  = ZP[k * 8 + v];
                ull cq = cconj(ZP[kn * 8 + m]);
                ull I  = cadd(p, cq);
                ull D  = csub(p, cq);
                ull E  = cscale(mneg_i(D), fo[u * 5 + v]);
                ull a  = fma2(HALF, I, ONE0);
                float ar, ai;
                unpack2(a, ar, ai);
                x[k] = fma2(pack2(ar, ar), E, cmul2(pack2(ai, ai), mpos_i(E)));
            }
            ull s0 = cadd(x[0], x[2]);
            ull s1 = csub(x[0], x[2]);
            ull s2 = cadd(x[1], x[3]);
            ull s3 = csub(x[1], x[3]);
            ull g0 = cadd(s0, s2);
            ull g2 = csub(s0, s2);
            ull wg = mpos_i(s3);
            ull g1 = cadd(s1, wg);
            ull g3 = csub(s1, wg);
            ull h0 = shfl64(g0, 16), h1 = shfl64(g1, 16);
            ull h2 = shfl64(g2, 16), h3 = shfl64(g3, 16);
            if (!hB) {
                ZP[0 * 8 + v] = cadd(g0, h0);
                ZP[1 * 8 + v] = fma2(C7P, cadd(h1, mpos_i(h1)), g1);
                ZP[2 * 8 + v] = cadd(g2, mpos_i(h2));
                ZP[3 * 8 + v] = fma2(C7P, mpos_i(cadd(h3, mpos_i(h3))), g3);
            } else {
                ZP[0 * 8 + v] = csub(h0, g0);
                ZP[1 * 8 + v] = fma2(NC7P, cadd(g1, mpos_i(g1)), h1);
                ZP[2 * 8 + v] = cadd(h2, mneg_i(g2));
                ZP[3 * 8 + v] = fma2(C7P, cadd(g3, mneg_i(g3)), h3);
            }
        }

        // stage C: paired real inverse (exact): ifft8(Za + i*Zb) = ra + i*rb
        __half* outp = g_xmid + (((size_t)(b * 128 + o) * 256 + ph * 8) * 256
                                 + pw16 * 16 + pp * 8);
#pragma unroll
        for (int jp = 0; jp < 2; jp++) {
            const int ja = 2 * jp, jb = 2 * jp + 1;
            const int Ra = h * 4 + ja;
            ull z[8];
#pragma unroll
            for (int v = 0; v < 5; v++)
                z[v] = cadd(ZP[ja * 8 + v], mpos_i(ZP[jb * 8 + v]));
            z[5] = cadd(cconj(ZP[ja * 8 + 3]), mpos_i(cconj(ZP[jb * 8 + 3])));
            z[6] = cadd(cconj(ZP[ja * 8 + 2]), mpos_i(cconj(ZP[jb * 8 + 2])));
            z[7] = cadd(cconj(ZP[ja * 8 + 1]), mpos_i(cconj(ZP[jb * 8 + 1])));
            cfft8p(z, false);
            __half2 ha[4], hb2[4];
#pragma unroll
            for (int tt = 0; tt < 4; tt++) {
                float lo0, hi0, lo1, hi1;
                unpack2(z[2 * tt], lo0, hi0);
                unpack2(z[2 * tt + 1], lo1, hi1);
                ha[tt]  = __floats2half2_rn(lo0, lo1);
                hb2[tt] = __floats2half2_rn(hi0, hi1);
            }
            *reinterpret_cast<uint4*>(outp + (size_t)Ra * 256) =
                *reinterpret_cast<uint4*>(ha);
            *reinterpret_cast<uint4*>(outp + (size_t)(Ra + 1) * 256) =
                *reinterpret_cast<uint4*>(hb2);
        }

        t = tn;
    }
}

// ---------------------------------------------------------------------------
// Kernel DW2: depthwise 3x3 (SAME) + exact GELU gate, vectorized fp16 halo.
// ---------------------------------------------------------------------------
__global__ void __launch_bounds__(256) kDW2(const float* __restrict__ w_dw)
{
    __shared__ __half sH2[2 * 18 * 80];

    const int tid = threadIdx.x;
    const int b = blockIdx.z >> 6, c = blockIdx.z & 63;
    const int x0 = blockIdx.x * 64, y0 = blockIdx.y * 16;

    float w1[9], w2[9];
#pragma unroll
    for (int j = 0; j < 9; j++) {
        w1[j] = w_dw[c * 9 + j];
        w2[j] = w_dw[(c + 64) * 9 + j];
    }

    const __half* src0 = g_xmid + (size_t)(b * 128 + c) * 65536;
    const __half* src1 = src0 + (size_t)64 * 65536;
    const __half zeroh = __float2half(0.f);

    for (int i = tid; i < 360; i += 256) {
        const int ch  = i / 180;
        const int rem = i - ch * 180;
        const int y = rem / 10, chk = rem - y * 10;
        const int gy = y0 + y - 1;
        const int gxc = x0 - 8 + chk * 8;
        uint4 v = make_uint4(0u, 0u, 0u, 0u);
        if (gy >= 0 && gy < 256) {
            const __half* src = (ch ? src1 : src0) + (size_t)gy * 256;
            if (gxc >= 0 && gxc + 8 <= 256) {
                v = *reinterpret_cast<const uint4*>(src + gxc);
            } else {
                __half2 h2[4];
#pragma unroll
                for (int e = 0; e < 4; e++) {
                    int g0 = gxc + 2 * e, g1 = g0 + 1;
                    __half a = (g0 >= 0 && g0 < 256) ? src[g0] : zeroh;
                    __half d = (g1 >= 0 && g1 < 256) ? src[g1] : zeroh;
                    h2[e] = __halves2half2(a, d);
                }
                v = *reinterpret_cast<uint4*>(h2);
            }
        }
        *reinterpret_cast<uint4*>(&sH2[ch * 1440 + y * 80 + chk * 8]) = v;
    }
    __syncthreads();

    const int px = tid & 63, ty = tid >> 6;
    __half* dst = g_gate + (size_t)(b * 64 + c) * 65536;
#pragma unroll
    for (int yy = 0; yy < 4; yy++) {
        int py = ty * 4 + yy;
        float a = 0.f, bb = 0.f;
#pragma unroll
        for (int dy = 0; dy < 3; dy++)
#pragma unroll
            for (int dx = 0; dx < 3; dx++) {
                const int hoff = (py + dy) * 80 + px + dx + 7;
                a  = fmaf(__half2float(sH2[hoff]),        w1[dy * 3 + dx], a);
                bb = fmaf(__half2float(sH2[1440 + hoff]), w2[dy * 3 + dx], bb);
            }
        float gl = 0.5f * a * (1.0f + erff(a * 0.70710678118654752f));
        dst[(size_t)(y0 + py) * 256 + x0 + px] = __float2half_rn(gl * bb);
    }
}

// ---------------------------------------------------------------------------
// Kernel Out3: persistent 1x1 projection (r14 version, grid 296).
// ---------------------------------------------------------------------------
__global__ void __launch_bounds__(256, 2) kOut3(const float* __restrict__ w_out,
                                                float* __restrict__ out)
{
    extern __shared__ float sm[];
    float* sG   = sm;          // [64][256]
    float* sWoT = sm + 16384;  // [64][64]

    const int tid    = threadIdx.x;
    const int stride = gridDim.x;

    for (int i = tid; i < 64 * 64; i += 256) {
        int k = i >> 6, o = i & 63;
        sWoT[k * 64 + o] = w_out[o * 64 + k];
    }

    const int ob = tid >> 5, pb = tid & 31;
    const int oc0 = ob * 8, p0 = pb * 8;

    for (int rr = blockIdx.x; rr < 1024; rr += stride) {
        const int b = rr >> 8, y = rr & 255;

        __syncthreads();
        for (int i = tid; i < 2048; i += 256) {
            int k = i >> 5, p8 = i & 31;
            uint4 rh = *reinterpret_cast<const uint4*>(
                g_gate + (size_t)(b * 64 + k) * 65536 + (size_t)y * 256 + p8 * 8);
            const __half2* hp = reinterpret_cast<const __half2*>(&rh);
            float v[8];
#pragma unroll
            for (int tt = 0; tt < 4; tt++) {
                float2 f2 = __half22float2(hp[tt]);
                v[2 * tt] = f2.x; v[2 * tt + 1] = f2.y;
            }
            float4 q0 = {v[0], v[1], v[2], v[3]};
            float4 q1 = {v[4], v[5], v[6], v[7]};
            *reinterpret_cast<float4*>(&sG[k * 256 + p8 * 8])     = q0;
            *reinterpret_cast<float4*>(&sG[k * 256 + p8 * 8 + 4]) = q1;
        }
        __syncthreads();

        ull acc[32];
#pragma unroll
        for (int i = 0; i < 32; i++) acc[i] = 0ULL;
#pragma unroll 8
        for (int k = 0; k < 64; k++) {
            float4 w0 = *reinterpret_cast<const float4*>(&sWoT[k * 64 + oc0]);
            float4 w1 = *reinterpret_cast<const float4*>(&sWoT[k * 64 + oc0 + 4]);
            ulonglong2 ga = *reinterpret_cast<const ulonglong2*>(&sG[k * 256 + p0]);
            ulonglong2 gb = *reinterpret_cast<const ulonglong2*>(&sG[k * 256 + p0 + 4]);
            ull gv[4] = {ga.x, ga.y, gb.x, gb.y};
            float wf[8] = {w0.x, w0.y, w0.z, w0.w, w1.x, w1.y, w1.z, w1.w};
#pragma unroll
            for (int i = 0; i < 8; i++) {
                ull wp = pack2(wf[i], wf[i]);
#pragma unroll
                for (int j = 0; j < 4; j++)
                    acc[i * 4 + j] = fma2(wp, gv[j], acc[i * 4 + j]);
            }
        }
#pragma unroll
        for (int i = 0; i < 8; i++) {
            float v[8];
#pragma unroll
            for (int j = 0; j < 4; j++) unpack2(acc[i * 4 + j], v[2 * j], v[2 * j + 1]);
            size_t gaddr = ((size_t)(b * 64 + oc0 + i) * 256 + y) * 256 + p0;
            float4 q0 = {v[0], v[1], v[2], v[3]};
            float4 q1 = {v[4], v[5], v[6], v[7]};
            *reinterpret_cast<float4*>(&out[gaddr])     = q0;
            *reinterpret_cast<float4*>(&out[gaddr + 4]) = q1;
        }
    }
}

// ---------------------------------------------------------------------------
extern "C" void kernel_launch(void* const* d_in, const int* in_sizes, int n_in,
                              void* d_out, int out_size)
{
    const float* img   = (const float*)d_in[0];
    const float* evt   = (const float*)d_in[1];
    const float* w_img = (const float*)d_in[2];
    const float* w_evt = (const float*)d_in[3];
    const float* w_dw  = (const float*)d_in[4];
    const float* filt  = (const float*)d_in[5];
    const float* w_out = (const float*)d_in[6];
    float* out = (float*)d_out;

    const int smemF = (13952) * 4 + 256 * MID_PITCH * 2;  // 125,440 B
    const int smemO = 20480 * 4;                          //  81,920 B
    cudaFuncSetAttribute(kF10,  cudaFuncAttributeMaxDynamicSharedMemorySize, smemF);
    cudaFuncSetAttribute(kOut3, cudaFuncAttributeMaxDynamicSharedMemorySize, smemO);

    kF10<<<296, 512, smemF>>>(img, evt, w_img, w_evt, filt);
    kDW2<<<dim3(4, 16, 256), 256>>>(w_dw);
    kOut3<<<296, 256, smemO>>>(w_out, out);
}